// round 9
// baseline (speedup 1.0000x reference)
#include <cuda_runtime.h>
#include <cuda_fp16.h>
#include <cstdint>

// ============================================================================
// SpikeMLP R9 = R7 GEMM config (STAGES=4, 1 CTA/SM) + two-phase fixup (R8)
//             + FLAG_EPS tightened to 4e-3 (proven escape-free in R6/R7).
// ============================================================================

#define STAGES 4
#define BM 128
#define BN 128
#define BK 64
#define STAGE_BYTES (BM * BK * 2)               // 16 KB
#define SMEM_B_OFF  (STAGES * STAGE_BYTES)      // 64 KB
#define SMEM_ALLOC  (2 * STAGES * STAGE_BYTES + 256)
#define HS_STRIDE 136                            // padded f32 row stride

#define FLAG_EPS 4e-3f
#define AMB_EPS  1e-4f
#define FLAG_CAP (1u << 22)

// ---------------- device scratch (no allocation allowed) -------------------
__device__ __align__(256) __half g_xh[16384UL * 512UL];        // 16 MB
__device__ __align__(256) __half g_w1h[2048UL * 512UL];        //  2 MB
__device__ __align__(256) __half g_w2h[512UL * 2048UL];        //  2 MB
__device__ __align__(256) __half g_spk[16384UL * 2048UL];      // 64 MB
__device__ unsigned int g_partial[2048];
__device__ unsigned int g_flags[FLAG_CAP];                      // 16 MB
__device__ unsigned int g_flag_count;
__device__ int          g_fix_delta;

// ---------------- PTX helpers ----------------------------------------------
__device__ __forceinline__ uint32_t smem_u32(const void* p) {
    uint32_t a;
    asm("{ .reg .u64 t; cvta.to.shared.u64 t, %1; cvt.u32.u64 %0, t; }"
        : "=r"(a) : "l"(p));
    return a;
}
__device__ __forceinline__ void cp16(uint32_t dst, const void* src) {
    asm volatile("cp.async.cg.shared.global [%0], [%1], 16;\n"
                 :: "r"(dst), "l"(src));
}
__device__ __forceinline__ void ldsm_x4(uint32_t r[4], uint32_t addr) {
    asm volatile("ldmatrix.sync.aligned.m8n8.x4.shared.b16 {%0,%1,%2,%3}, [%4];\n"
                 : "=r"(r[0]), "=r"(r[1]), "=r"(r[2]), "=r"(r[3]) : "r"(addr));
}
__device__ __forceinline__ void mma16816(float c[4], const uint32_t a[4],
                                         const uint32_t* b) {
    asm volatile(
        "mma.sync.aligned.m16n8k16.row.col.f32.f16.f16.f32 "
        "{%0,%1,%2,%3}, {%4,%5,%6,%7}, {%8,%9}, {%0,%1,%2,%3};\n"
        : "+f"(c[0]), "+f"(c[1]), "+f"(c[2]), "+f"(c[3])
        : "r"(a[0]), "r"(a[1]), "r"(a[2]), "r"(a[3]), "r"(b[0]), "r"(b[1]));
}

// ============================================================================
// GEMM1 fused with LIF (tile rows = 4 timesteps x 32 seq of one batch)
// ============================================================================
__global__ __launch_bounds__(256, 1) void gemm1_lif(
    const __half* __restrict__ A, const __half* __restrict__ B)
{
    extern __shared__ uint8_t dynsmem[];
    const uint32_t base = (smem_u32(dynsmem) + 127u) & ~127u;

    const int tid  = threadIdx.x;
    const int wid  = tid >> 5;
    const int lane = tid & 31;
    const int b    = blockIdx.y >> 3;
    const int s0   = (blockIdx.y & 7) * 32;
    const int n0   = blockIdx.x * BN;
    const int warp_m = (wid >> 2) * 64;
    const int warp_n = (wid & 3) * 32;

    int a_rb[4], a_xr[4];
    #pragma unroll
    for (int mt = 0; mt < 4; mt++) {
        const int r = warp_m + mt * 16 + (lane & 15);
        a_rb[mt] = r * 128;
        a_xr[mt] = (r & 7) << 4;
    }
    const int a_c0 = (lane >> 4) * 16;
    int b_rb[2], b_xr[2];
    {
        const int rl = (lane & 7) + ((lane >> 4) << 3);
        #pragma unroll
        for (int p = 0; p < 2; p++) {
            const int r = warp_n + p * 16 + rl;
            b_rb[p] = r * 128;
            b_xr[p] = (r & 7) << 4;
        }
    }
    const int b_c0 = ((lane >> 3) & 1) * 16;

    auto load_chunk = [&](int chunk, int slot) {
        const int k0 = chunk * BK;
        const uint32_t sA = base + slot * STAGE_BYTES;
        const uint32_t sB = base + SMEM_B_OFF + slot * STAGE_BYTES;
        #pragma unroll
        for (int r = 0; r < 4; r++) {
            const int idx = tid + r * 256;
            const int row = idx >> 3;
            const int cb  = (idx & 7) * 16;
            const int ga = b * 1024 + (row >> 5) * 256 + s0 + (row & 31);
            cp16(sA + row * 128 + (cb ^ ((row & 7) << 4)),
                 A + (size_t)ga * 512 + k0 + (cb >> 1));
            cp16(sB + row * 128 + (cb ^ ((row & 7) << 4)),
                 B + (size_t)(n0 + row) * 512 + k0 + (cb >> 1));
        }
    };

    float acc[4][4][4];
    #pragma unroll
    for (int mt = 0; mt < 4; mt++)
        #pragma unroll
        for (int nt = 0; nt < 4; nt++)
            #pragma unroll
            for (int q = 0; q < 4; q++) acc[mt][nt][q] = 0.0f;

    #pragma unroll
    for (int j = 0; j < STAGES - 1; j++) {
        load_chunk(j, j);
        asm volatile("cp.async.commit_group;\n" ::: "memory");
    }

    const int nchunks = 512 / BK;   // 8
    for (int i = 0; i < nchunks; i++) {
        asm volatile("cp.async.wait_group %0;\n" :: "n"(STAGES - 2));
        __syncthreads();
        const int lc = i + STAGES - 1;
        if (lc < nchunks) load_chunk(lc, lc & (STAGES - 1));
        asm volatile("cp.async.commit_group;\n" ::: "memory");

        const uint32_t sA = base + (i & (STAGES - 1)) * STAGE_BYTES;
        const uint32_t sB = base + SMEM_B_OFF + (i & (STAGES - 1)) * STAGE_BYTES;

        uint32_t af[2][4][4], bf[2][2][4];
        #pragma unroll
        for (int mt = 0; mt < 4; mt++)
            ldsm_x4(af[0][mt], sA + a_rb[mt] + ((a_c0) ^ a_xr[mt]));
        #pragma unroll
        for (int p = 0; p < 2; p++)
            ldsm_x4(bf[0][p], sB + b_rb[p] + ((b_c0) ^ b_xr[p]));

        #pragma unroll
        for (int ks = 0; ks < 4; ks++) {
            const int cur = ks & 1, nxt = cur ^ 1;
            if (ks < 3) {
                const int c = (ks + 1) * 32;
                #pragma unroll
                for (int mt = 0; mt < 4; mt++)
                    ldsm_x4(af[nxt][mt], sA + a_rb[mt] + ((c + a_c0) ^ a_xr[mt]));
                #pragma unroll
                for (int p = 0; p < 2; p++)
                    ldsm_x4(bf[nxt][p], sB + b_rb[p] + ((c + b_c0) ^ b_xr[p]));
            }
            #pragma unroll
            for (int mt = 0; mt < 4; mt++)
                #pragma unroll
                for (int nt = 0; nt < 4; nt++)
                    mma16816(acc[mt][nt], af[cur][mt],
                             &bf[cur][nt >> 1][(nt & 1) * 2]);
        }
    }

    // ---- epilogue: acc -> smem f32 tile, in-block LIF scan -----------------
    __syncthreads();
    float* hs = (float*)(dynsmem + ((128 - ((uintptr_t)dynsmem & 127)) & 127));
    #pragma unroll
    for (int mt = 0; mt < 4; mt++) {
        const int row = warp_m + mt * 16 + (lane >> 2);
        #pragma unroll
        for (int nt = 0; nt < 4; nt++) {
            const int col = warp_n + nt * 8 + (lane & 3) * 2;
            *(float2*)&hs[(size_t)row * HS_STRIDE + col] =
                make_float2(acc[mt][nt][0], acc[mt][nt][1]);
            *(float2*)&hs[(size_t)(row + 8) * HS_STRIDE + col] =
                make_float2(acc[mt][nt][2], acc[mt][nt][3]);
        }
    }
    __syncthreads();

    const float beta = (float)(1.0 - 1.0 / 20.0);
    const __half one  = __float2half(1.0f);
    const __half zero = __float2half(0.0f);
    int cnt = 0;

    #pragma unroll
    for (int iter = 0; iter < 16; iter++) {
        const int s   = (iter << 1) | (tid >> 7);
        const int col = tid & 127;
        float v = 0.0f;
        bool flagged = false;
        #pragma unroll
        for (int t = 0; t < 4; t++) {
            const float h = hs[(size_t)(t * 32 + s) * HS_STRIDE + col];
            v = fmaf(beta, v, h);
            flagged |= (fabsf(v - 1.0f) < FLAG_EPS);
            const bool fire = (v > 1.0f);
            g_spk[((size_t)(b * 4 + t) * 256 + s0 + s) * 2048 + n0 + col] =
                fire ? one : zero;
            cnt += fire ? 1 : 0;
            v = fire ? 0.0f : v;
        }
        const unsigned int mask = __ballot_sync(0xFFFFFFFFu, flagged);
        if (flagged) {
            const int leader = __ffs(mask) - 1;
            const int rank   = __popc(mask & ((1u << lane) - 1));
            unsigned int pos = 0;
            if (lane == leader) pos = atomicAdd(&g_flag_count, __popc(mask));
            pos = __shfl_sync(mask, pos, leader);
            const unsigned int nidx =
                (unsigned int)(((b * 256 + s0 + s) << 11) + n0 + col);
            if (pos + rank < FLAG_CAP) g_flags[pos + rank] = nidx;
        }
    }

    #pragma unroll
    for (int o = 16; o; o >>= 1) cnt += __shfl_down_sync(0xFFFFFFFFu, cnt, o);
    __shared__ int warpsum[8];
    if (lane == 0) warpsum[wid] = cnt;
    __syncthreads();
    if (tid == 0) {
        int tot = 0;
        #pragma unroll
        for (int w = 0; w < 8; w++) tot += warpsum[w];
        g_partial[blockIdx.y * 16 + blockIdx.x] = (unsigned int)tot;
    }
}

// ============================================================================
// fp16 NT GEMM (GEMM2)
// ============================================================================
__global__ __launch_bounds__(256, 1) void gemm_f16(
    const __half* __restrict__ A, const __half* __restrict__ B,
    float* __restrict__ C, int ldc, int nchunks, int a_rs, int b_rs)
{
    extern __shared__ uint8_t dynsmem[];
    const uint32_t base = (smem_u32(dynsmem) + 127u) & ~127u;

    const int tid  = threadIdx.x;
    const int wid  = tid >> 5;
    const int lane = tid & 31;
    const int m0   = blockIdx.y * BM;
    const int n0   = blockIdx.x * BN;
    const int warp_m = (wid >> 2) * 64;
    const int warp_n = (wid & 3) * 32;

    int a_rb[4], a_xr[4];
    #pragma unroll
    for (int mt = 0; mt < 4; mt++) {
        const int r = warp_m + mt * 16 + (lane & 15);
        a_rb[mt] = r * 128;
        a_xr[mt] = (r & 7) << 4;
    }
    const int a_c0 = (lane >> 4) * 16;
    int b_rb[2], b_xr[2];
    {
        const int rl = (lane & 7) + ((lane >> 4) << 3);
        #pragma unroll
        for (int p = 0; p < 2; p++) {
            const int r = warp_n + p * 16 + rl;
            b_rb[p] = r * 128;
            b_xr[p] = (r & 7) << 4;
        }
    }
    const int b_c0 = ((lane >> 3) & 1) * 16;

    auto load_chunk = [&](int chunk, int slot) {
        const int k0 = chunk * BK;
        const uint32_t sA = base + slot * STAGE_BYTES;
        const uint32_t sB = base + SMEM_B_OFF + slot * STAGE_BYTES;
        #pragma unroll
        for (int r = 0; r < 4; r++) {
            const int idx = tid + r * 256;
            const int row = idx >> 3;
            const int cb  = (idx & 7) * 16;
            cp16(sA + row * 128 + (cb ^ ((row & 7) << 4)),
                 A + (size_t)(m0 + row) * a_rs + k0 + (cb >> 1));
            cp16(sB + row * 128 + (cb ^ ((row & 7) << 4)),
                 B + (size_t)(n0 + row) * b_rs + k0 + (cb >> 1));
        }
    };

    float acc[4][4][4];
    #pragma unroll
    for (int mt = 0; mt < 4; mt++)
        #pragma unroll
        for (int nt = 0; nt < 4; nt++)
            #pragma unroll
            for (int q = 0; q < 4; q++) acc[mt][nt][q] = 0.0f;

    #pragma unroll
    for (int j = 0; j < STAGES - 1; j++) {
        load_chunk(j, j);
        asm volatile("cp.async.commit_group;\n" ::: "memory");
    }

    for (int i = 0; i < nchunks; i++) {
        asm volatile("cp.async.wait_group %0;\n" :: "n"(STAGES - 2));
        __syncthreads();
        const int lc = i + STAGES - 1;
        if (lc < nchunks) load_chunk(lc, lc & (STAGES - 1));
        asm volatile("cp.async.commit_group;\n" ::: "memory");

        const uint32_t sA = base + (i & (STAGES - 1)) * STAGE_BYTES;
        const uint32_t sB = base + SMEM_B_OFF + (i & (STAGES - 1)) * STAGE_BYTES;

        uint32_t af[2][4][4], bf[2][2][4];
        #pragma unroll
        for (int mt = 0; mt < 4; mt++)
            ldsm_x4(af[0][mt], sA + a_rb[mt] + ((a_c0) ^ a_xr[mt]));
        #pragma unroll
        for (int p = 0; p < 2; p++)
            ldsm_x4(bf[0][p], sB + b_rb[p] + ((b_c0) ^ b_xr[p]));

        #pragma unroll
        for (int ks = 0; ks < 4; ks++) {
            const int cur = ks & 1, nxt = cur ^ 1;
            if (ks < 3) {
                const int c = (ks + 1) * 32;
                #pragma unroll
                for (int mt = 0; mt < 4; mt++)
                    ldsm_x4(af[nxt][mt], sA + a_rb[mt] + ((c + a_c0) ^ a_xr[mt]));
                #pragma unroll
                for (int p = 0; p < 2; p++)
                    ldsm_x4(bf[nxt][p], sB + b_rb[p] + ((c + b_c0) ^ b_xr[p]));
            }
            #pragma unroll
            for (int mt = 0; mt < 4; mt++)
                #pragma unroll
                for (int nt = 0; nt < 4; nt++)
                    mma16816(acc[mt][nt], af[cur][mt],
                             &bf[cur][nt >> 1][(nt & 1) * 2]);
        }
    }

    #pragma unroll
    for (int mt = 0; mt < 4; mt++) {
        #pragma unroll
        for (int nt = 0; nt < 4; nt++) {
            const int row = m0 + warp_m + mt * 16 + (lane >> 2);
            const int col = n0 + warp_n + nt * 8 + (lane & 3) * 2;
            float* c0 = C + (size_t)row * ldc + col;
            float* c1 = C + (size_t)(row + 8) * ldc + col;
            *(float2*)c0 = make_float2(acc[mt][nt][0], acc[mt][nt][1]);
            *(float2*)c1 = make_float2(acc[mt][nt][2], acc[mt][nt][3]);
        }
    }
}

// ============================================================================
__global__ __launch_bounds__(256) void cvt_f16(const float* __restrict__ src,
                                               __half* __restrict__ dst)
{
    const size_t i = ((size_t)blockIdx.x * 256 + threadIdx.x) * 4;
    const float4 v = *(const float4*)(src + i);
    *(__half2*)(dst + i)     = __floats2half2_rn(v.x, v.y);
    *(__half2*)(dst + i + 2) = __floats2half2_rn(v.z, v.w);
}

__global__ void reset_kernel()
{
    g_flag_count = 0;
    g_fix_delta = 0;
}

// ============================================================================
// Two-phase fixup: warp butterfly dots; ambiguous neurons (|v-1| < AMB_EPS)
// redone by lane 0 with exact sequential ascending-k fp32 fma.
// ============================================================================
__global__ __launch_bounds__(256) void fixup_kernel(
    const float* __restrict__ x, const float* __restrict__ w1)
{
    const unsigned int n = min(g_flag_count, (unsigned int)FLAG_CAP);
    const int lane = threadIdx.x & 31;
    const unsigned int warp = (blockIdx.x * 256 + threadIdx.x) >> 5;
    const unsigned int nwarps = (gridDim.x * 256) >> 5;
    int delta = 0;

    const float beta = (float)(1.0 - 1.0 / 20.0);
    const __half one  = __float2half(1.0f);
    const __half zero = __float2half(0.0f);

    for (unsigned int i = warp; i < n; i += nwarps) {
        const unsigned int idx = g_flags[i];
        const int    hid = (int)(idx & 2047u);
        const size_t bs  = idx >> 11;
        const size_t b   = bs >> 8;
        const size_t s   = bs & 255;
        const size_t bse = ((b * 4) * 256 + s) * 2048 + hid;
        const size_t ts  = 256UL * 2048UL;

        const float4* wrow = (const float4*)(w1 + (size_t)hid * 512);
        float w[16];
        #pragma unroll
        for (int j = 0; j < 4; j++) {
            const float4 wv = wrow[lane + j * 32];
            w[j * 4 + 0] = wv.x; w[j * 4 + 1] = wv.y;
            w[j * 4 + 2] = wv.z; w[j * 4 + 3] = wv.w;
        }

        float accs[4];
        #pragma unroll
        for (int t = 0; t < 4; t++) {
            const float4* xrow =
                (const float4*)(x + (((b * 4 + t) * 256 + s) << 9));
            float a = 0.0f;
            #pragma unroll
            for (int j = 0; j < 4; j++) {
                const float4 xv = xrow[lane + j * 32];
                a = fmaf(xv.x, w[j * 4 + 0], a);
                a = fmaf(xv.y, w[j * 4 + 1], a);
                a = fmaf(xv.z, w[j * 4 + 2], a);
                a = fmaf(xv.w, w[j * 4 + 3], a);
            }
            #pragma unroll
            for (int o = 16; o; o >>= 1)
                a += __shfl_xor_sync(0xFFFFFFFFu, a, o);
            accs[t] = a;
        }

        if (lane == 0) {
            bool amb = false;
            {
                float v = 0.0f;
                #pragma unroll
                for (int t = 0; t < 4; t++) {
                    v = fmaf(beta, v, accs[t]);
                    amb |= (fabsf(v - 1.0f) < AMB_EPS);
                    v = (v > 1.0f) ? 0.0f : v;
                }
            }
            if (amb) {
                const float* wr = w1 + (size_t)hid * 512;
                #pragma unroll
                for (int t = 0; t < 4; t++) {
                    const float* xr = x + (((b * 4 + t) * 256 + s) << 9);
                    float a = 0.0f;
                    #pragma unroll 8
                    for (int k = 0; k < 512; k++) a = fmaf(xr[k], wr[k], a);
                    accs[t] = a;
                }
            }
            float v = 0.0f;
            #pragma unroll
            for (int t = 0; t < 4; t++) {
                v = fmaf(beta, v, accs[t]);
                const bool fire = (v > 1.0f);
                const __half old = g_spk[bse + (size_t)t * ts];
                const bool oldf = (__half2float(old) > 0.5f);
                if (fire != oldf) {
                    g_spk[bse + (size_t)t * ts] = fire ? one : zero;
                    delta += fire ? 1 : -1;
                }
                v = fire ? 0.0f : v;
            }
        }
    }

    #pragma unroll
    for (int o = 16; o; o >>= 1) delta += __shfl_down_sync(0xFFFFFFFFu, delta, o);
    __shared__ int wsum[8];
    if (lane == 0) wsum[threadIdx.x >> 5] = delta;
    __syncthreads();
    if (threadIdx.x == 0) {
        int tot = 0;
        #pragma unroll
        for (int w = 0; w < 8; w++) tot += wsum[w];
        if (tot != 0) atomicAdd(&g_fix_delta, tot);
    }
}

__global__ __launch_bounds__(1024) void rate_kernel(float* __restrict__ out_rate)
{
    long long s = 0;
    for (int i = threadIdx.x; i < 2048; i += 1024) s += g_partial[i];
    #pragma unroll
    for (int o = 16; o; o >>= 1) s += __shfl_down_sync(0xFFFFFFFFu, s, o);
    __shared__ long long sh[32];
    if ((threadIdx.x & 31) == 0) sh[threadIdx.x >> 5] = s;
    __syncthreads();
    if (threadIdx.x == 0) {
        long long tot = 0;
        #pragma unroll
        for (int w = 0; w < 32; w++) tot += sh[w];
        tot += g_fix_delta;
        *out_rate = (float)((double)tot / 33554432.0);
    }
}

// ============================================================================
extern "C" void kernel_launch(void* const* d_in, const int* in_sizes, int n_in,
                              void* d_out, int out_size)
{
    const float* x  = (const float*)d_in[0];
    const float* w1 = (const float*)d_in[1];
    const float* w2 = (const float*)d_in[2];
    float* out = (float*)d_out;

    __half *xh, *w1h, *w2h, *spk;
    cudaGetSymbolAddress((void**)&xh,  g_xh);
    cudaGetSymbolAddress((void**)&w1h, g_w1h);
    cudaGetSymbolAddress((void**)&w2h, g_w2h);
    cudaGetSymbolAddress((void**)&spk, g_spk);

    cudaFuncSetAttribute(gemm1_lif, cudaFuncAttributeMaxDynamicSharedMemorySize,
                         SMEM_ALLOC);
    cudaFuncSetAttribute(gemm_f16, cudaFuncAttributeMaxDynamicSharedMemorySize,
                         SMEM_ALLOC);

    reset_kernel<<<1, 1>>>();

    cvt_f16<<<8192, 256>>>(x,  xh);
    cvt_f16<<<1024, 256>>>(w1, w1h);
    cvt_f16<<<1024, 256>>>(w2, w2h);

    // GEMM1 + LIF fused
    gemm1_lif<<<dim3(16, 128), 256, SMEM_ALLOC>>>(xh, w1h);

    // two-phase fixup, then rate
    fixup_kernel<<<1184, 256>>>(x, w1);
    rate_kernel<<<1, 1024>>>(out + (out_size - 1));

    // GEMM2
    gemm_f16<<<dim3(512 / BN, 16384 / BM), 256, SMEM_ALLOC>>>(
        spk, w2h, out, 512, 2048 / BK, 2048, 2048);
}

// round 10
// speedup vs baseline: 1.1438x; 1.1438x over previous
#include <cuda_runtime.h>
#include <cuda_fp16.h>
#include <cstdint>

// ============================================================================
// SpikeMLP R10: R7 GEMM config + two-phase fixup with smem-staged phase B.
//   GEMM1+LIF fused (tile = 4 timesteps x 32 seq of one batch), FLAG_EPS 4e-3.
//   FIXUP: phase A warp butterfly; ambiguous (|v-1|<1e-4) neurons re-resolved
//     by lane 0 with the exact ascending-k fp32 fma order, operands staged
//     into shared memory by the whole warp (coalesced) first.
//   GEMM2: out = spk @ fp16(w2)^T.
// ============================================================================

#define STAGES 4
#define BM 128
#define BN 128
#define BK 64
#define STAGE_BYTES (BM * BK * 2)               // 16 KB
#define SMEM_B_OFF  (STAGES * STAGE_BYTES)      // 64 KB
#define SMEM_ALLOC  (2 * STAGES * STAGE_BYTES + 256)
#define HS_STRIDE 136                            // padded f32 row stride

#define FLAG_EPS 4e-3f
#define AMB_EPS  1e-4f
#define FLAG_CAP (1u << 22)

// ---------------- device scratch (no allocation allowed) -------------------
__device__ __align__(256) __half g_xh[16384UL * 512UL];        // 16 MB
__device__ __align__(256) __half g_w1h[2048UL * 512UL];        //  2 MB
__device__ __align__(256) __half g_w2h[512UL * 2048UL];        //  2 MB
__device__ __align__(256) __half g_spk[16384UL * 2048UL];      // 64 MB
__device__ unsigned int g_partial[2048];
__device__ unsigned int g_flags[FLAG_CAP];                      // 16 MB
__device__ unsigned int g_flag_count;
__device__ int          g_fix_delta;

// ---------------- PTX helpers ----------------------------------------------
__device__ __forceinline__ uint32_t smem_u32(const void* p) {
    uint32_t a;
    asm("{ .reg .u64 t; cvta.to.shared.u64 t, %1; cvt.u32.u64 %0, t; }"
        : "=r"(a) : "l"(p));
    return a;
}
__device__ __forceinline__ void cp16(uint32_t dst, const void* src) {
    asm volatile("cp.async.cg.shared.global [%0], [%1], 16;\n"
                 :: "r"(dst), "l"(src));
}
__device__ __forceinline__ void ldsm_x4(uint32_t r[4], uint32_t addr) {
    asm volatile("ldmatrix.sync.aligned.m8n8.x4.shared.b16 {%0,%1,%2,%3}, [%4];\n"
                 : "=r"(r[0]), "=r"(r[1]), "=r"(r[2]), "=r"(r[3]) : "r"(addr));
}
__device__ __forceinline__ void mma16816(float c[4], const uint32_t a[4],
                                         const uint32_t* b) {
    asm volatile(
        "mma.sync.aligned.m16n8k16.row.col.f32.f16.f16.f32 "
        "{%0,%1,%2,%3}, {%4,%5,%6,%7}, {%8,%9}, {%0,%1,%2,%3};\n"
        : "+f"(c[0]), "+f"(c[1]), "+f"(c[2]), "+f"(c[3])
        : "r"(a[0]), "r"(a[1]), "r"(a[2]), "r"(a[3]), "r"(b[0]), "r"(b[1]));
}

// ============================================================================
// GEMM1 fused with LIF (tile rows = 4 timesteps x 32 seq of one batch)
// ============================================================================
__global__ __launch_bounds__(256, 1) void gemm1_lif(
    const __half* __restrict__ A, const __half* __restrict__ B)
{
    extern __shared__ uint8_t dynsmem[];
    const uint32_t base = (smem_u32(dynsmem) + 127u) & ~127u;

    const int tid  = threadIdx.x;
    const int wid  = tid >> 5;
    const int lane = tid & 31;
    const int b    = blockIdx.y >> 3;
    const int s0   = (blockIdx.y & 7) * 32;
    const int n0   = blockIdx.x * BN;
    const int warp_m = (wid >> 2) * 64;
    const int warp_n = (wid & 3) * 32;

    int a_rb[4], a_xr[4];
    #pragma unroll
    for (int mt = 0; mt < 4; mt++) {
        const int r = warp_m + mt * 16 + (lane & 15);
        a_rb[mt] = r * 128;
        a_xr[mt] = (r & 7) << 4;
    }
    const int a_c0 = (lane >> 4) * 16;
    int b_rb[2], b_xr[2];
    {
        const int rl = (lane & 7) + ((lane >> 4) << 3);
        #pragma unroll
        for (int p = 0; p < 2; p++) {
            const int r = warp_n + p * 16 + rl;
            b_rb[p] = r * 128;
            b_xr[p] = (r & 7) << 4;
        }
    }
    const int b_c0 = ((lane >> 3) & 1) * 16;

    auto load_chunk = [&](int chunk, int slot) {
        const int k0 = chunk * BK;
        const uint32_t sA = base + slot * STAGE_BYTES;
        const uint32_t sB = base + SMEM_B_OFF + slot * STAGE_BYTES;
        #pragma unroll
        for (int r = 0; r < 4; r++) {
            const int idx = tid + r * 256;
            const int row = idx >> 3;
            const int cb  = (idx & 7) * 16;
            const int ga = b * 1024 + (row >> 5) * 256 + s0 + (row & 31);
            cp16(sA + row * 128 + (cb ^ ((row & 7) << 4)),
                 A + (size_t)ga * 512 + k0 + (cb >> 1));
            cp16(sB + row * 128 + (cb ^ ((row & 7) << 4)),
                 B + (size_t)(n0 + row) * 512 + k0 + (cb >> 1));
        }
    };

    float acc[4][4][4];
    #pragma unroll
    for (int mt = 0; mt < 4; mt++)
        #pragma unroll
        for (int nt = 0; nt < 4; nt++)
            #pragma unroll
            for (int q = 0; q < 4; q++) acc[mt][nt][q] = 0.0f;

    #pragma unroll
    for (int j = 0; j < STAGES - 1; j++) {
        load_chunk(j, j);
        asm volatile("cp.async.commit_group;\n" ::: "memory");
    }

    const int nchunks = 512 / BK;   // 8
    for (int i = 0; i < nchunks; i++) {
        asm volatile("cp.async.wait_group %0;\n" :: "n"(STAGES - 2));
        __syncthreads();
        const int lc = i + STAGES - 1;
        if (lc < nchunks) load_chunk(lc, lc & (STAGES - 1));
        asm volatile("cp.async.commit_group;\n" ::: "memory");

        const uint32_t sA = base + (i & (STAGES - 1)) * STAGE_BYTES;
        const uint32_t sB = base + SMEM_B_OFF + (i & (STAGES - 1)) * STAGE_BYTES;

        uint32_t af[2][4][4], bf[2][2][4];
        #pragma unroll
        for (int mt = 0; mt < 4; mt++)
            ldsm_x4(af[0][mt], sA + a_rb[mt] + ((a_c0) ^ a_xr[mt]));
        #pragma unroll
        for (int p = 0; p < 2; p++)
            ldsm_x4(bf[0][p], sB + b_rb[p] + ((b_c0) ^ b_xr[p]));

        #pragma unroll
        for (int ks = 0; ks < 4; ks++) {
            const int cur = ks & 1, nxt = cur ^ 1;
            if (ks < 3) {
                const int c = (ks + 1) * 32;
                #pragma unroll
                for (int mt = 0; mt < 4; mt++)
                    ldsm_x4(af[nxt][mt], sA + a_rb[mt] + ((c + a_c0) ^ a_xr[mt]));
                #pragma unroll
                for (int p = 0; p < 2; p++)
                    ldsm_x4(bf[nxt][p], sB + b_rb[p] + ((c + b_c0) ^ b_xr[p]));
            }
            #pragma unroll
            for (int mt = 0; mt < 4; mt++)
                #pragma unroll
                for (int nt = 0; nt < 4; nt++)
                    mma16816(acc[mt][nt], af[cur][mt],
                             &bf[cur][nt >> 1][(nt & 1) * 2]);
        }
    }

    // ---- epilogue: acc -> smem f32 tile, in-block LIF scan -----------------
    __syncthreads();
    float* hs = (float*)(dynsmem + ((128 - ((uintptr_t)dynsmem & 127)) & 127));
    #pragma unroll
    for (int mt = 0; mt < 4; mt++) {
        const int row = warp_m + mt * 16 + (lane >> 2);
        #pragma unroll
        for (int nt = 0; nt < 4; nt++) {
            const int col = warp_n + nt * 8 + (lane & 3) * 2;
            *(float2*)&hs[(size_t)row * HS_STRIDE + col] =
                make_float2(acc[mt][nt][0], acc[mt][nt][1]);
            *(float2*)&hs[(size_t)(row + 8) * HS_STRIDE + col] =
                make_float2(acc[mt][nt][2], acc[mt][nt][3]);
        }
    }
    __syncthreads();

    const float beta = (float)(1.0 - 1.0 / 20.0);
    const __half one  = __float2half(1.0f);
    const __half zero = __float2half(0.0f);
    int cnt = 0;

    #pragma unroll
    for (int iter = 0; iter < 16; iter++) {
        const int s   = (iter << 1) | (tid >> 7);
        const int col = tid & 127;
        float v = 0.0f;
        bool flagged = false;
        #pragma unroll
        for (int t = 0; t < 4; t++) {
            const float h = hs[(size_t)(t * 32 + s) * HS_STRIDE + col];
            v = fmaf(beta, v, h);
            flagged |= (fabsf(v - 1.0f) < FLAG_EPS);
            const bool fire = (v > 1.0f);
            g_spk[((size_t)(b * 4 + t) * 256 + s0 + s) * 2048 + n0 + col] =
                fire ? one : zero;
            cnt += fire ? 1 : 0;
            v = fire ? 0.0f : v;
        }
        const unsigned int mask = __ballot_sync(0xFFFFFFFFu, flagged);
        if (flagged) {
            const int leader = __ffs(mask) - 1;
            const int rank   = __popc(mask & ((1u << lane) - 1));
            unsigned int pos = 0;
            if (lane == leader) pos = atomicAdd(&g_flag_count, __popc(mask));
            pos = __shfl_sync(mask, pos, leader);
            const unsigned int nidx =
                (unsigned int)(((b * 256 + s0 + s) << 11) + n0 + col);
            if (pos + rank < FLAG_CAP) g_flags[pos + rank] = nidx;
        }
    }

    #pragma unroll
    for (int o = 16; o; o >>= 1) cnt += __shfl_down_sync(0xFFFFFFFFu, cnt, o);
    __shared__ int warpsum[8];
    if (lane == 0) warpsum[wid] = cnt;
    __syncthreads();
    if (tid == 0) {
        int tot = 0;
        #pragma unroll
        for (int w = 0; w < 8; w++) tot += warpsum[w];
        g_partial[blockIdx.y * 16 + blockIdx.x] = (unsigned int)tot;
    }
}

// ============================================================================
// fp16 NT GEMM (GEMM2)
// ============================================================================
__global__ __launch_bounds__(256, 1) void gemm_f16(
    const __half* __restrict__ A, const __half* __restrict__ B,
    float* __restrict__ C, int ldc, int nchunks, int a_rs, int b_rs)
{
    extern __shared__ uint8_t dynsmem[];
    const uint32_t base = (smem_u32(dynsmem) + 127u) & ~127u;

    const int tid  = threadIdx.x;
    const int wid  = tid >> 5;
    const int lane = tid & 31;
    const int m0   = blockIdx.y * BM;
    const int n0   = blockIdx.x * BN;
    const int warp_m = (wid >> 2) * 64;
    const int warp_n = (wid & 3) * 32;

    int a_rb[4], a_xr[4];
    #pragma unroll
    for (int mt = 0; mt < 4; mt++) {
        const int r = warp_m + mt * 16 + (lane & 15);
        a_rb[mt] = r * 128;
        a_xr[mt] = (r & 7) << 4;
    }
    const int a_c0 = (lane >> 4) * 16;
    int b_rb[2], b_xr[2];
    {
        const int rl = (lane & 7) + ((lane >> 4) << 3);
        #pragma unroll
        for (int p = 0; p < 2; p++) {
            const int r = warp_n + p * 16 + rl;
            b_rb[p] = r * 128;
            b_xr[p] = (r & 7) << 4;
        }
    }
    const int b_c0 = ((lane >> 3) & 1) * 16;

    auto load_chunk = [&](int chunk, int slot) {
        const int k0 = chunk * BK;
        const uint32_t sA = base + slot * STAGE_BYTES;
        const uint32_t sB = base + SMEM_B_OFF + slot * STAGE_BYTES;
        #pragma unroll
        for (int r = 0; r < 4; r++) {
            const int idx = tid + r * 256;
            const int row = idx >> 3;
            const int cb  = (idx & 7) * 16;
            cp16(sA + row * 128 + (cb ^ ((row & 7) << 4)),
                 A + (size_t)(m0 + row) * a_rs + k0 + (cb >> 1));
            cp16(sB + row * 128 + (cb ^ ((row & 7) << 4)),
                 B + (size_t)(n0 + row) * b_rs + k0 + (cb >> 1));
        }
    };

    float acc[4][4][4];
    #pragma unroll
    for (int mt = 0; mt < 4; mt++)
        #pragma unroll
        for (int nt = 0; nt < 4; nt++)
            #pragma unroll
            for (int q = 0; q < 4; q++) acc[mt][nt][q] = 0.0f;

    #pragma unroll
    for (int j = 0; j < STAGES - 1; j++) {
        load_chunk(j, j);
        asm volatile("cp.async.commit_group;\n" ::: "memory");
    }

    for (int i = 0; i < nchunks; i++) {
        asm volatile("cp.async.wait_group %0;\n" :: "n"(STAGES - 2));
        __syncthreads();
        const int lc = i + STAGES - 1;
        if (lc < nchunks) load_chunk(lc, lc & (STAGES - 1));
        asm volatile("cp.async.commit_group;\n" ::: "memory");

        const uint32_t sA = base + (i & (STAGES - 1)) * STAGE_BYTES;
        const uint32_t sB = base + SMEM_B_OFF + (i & (STAGES - 1)) * STAGE_BYTES;

        uint32_t af[2][4][4], bf[2][2][4];
        #pragma unroll
        for (int mt = 0; mt < 4; mt++)
            ldsm_x4(af[0][mt], sA + a_rb[mt] + ((a_c0) ^ a_xr[mt]));
        #pragma unroll
        for (int p = 0; p < 2; p++)
            ldsm_x4(bf[0][p], sB + b_rb[p] + ((b_c0) ^ b_xr[p]));

        #pragma unroll
        for (int ks = 0; ks < 4; ks++) {
            const int cur = ks & 1, nxt = cur ^ 1;
            if (ks < 3) {
                const int c = (ks + 1) * 32;
                #pragma unroll
                for (int mt = 0; mt < 4; mt++)
                    ldsm_x4(af[nxt][mt], sA + a_rb[mt] + ((c + a_c0) ^ a_xr[mt]));
                #pragma unroll
                for (int p = 0; p < 2; p++)
                    ldsm_x4(bf[nxt][p], sB + b_rb[p] + ((c + b_c0) ^ b_xr[p]));
            }
            #pragma unroll
            for (int mt = 0; mt < 4; mt++)
                #pragma unroll
                for (int nt = 0; nt < 4; nt++)
                    mma16816(acc[mt][nt], af[cur][mt],
                             &bf[cur][nt >> 1][(nt & 1) * 2]);
        }
    }

    #pragma unroll
    for (int mt = 0; mt < 4; mt++) {
        #pragma unroll
        for (int nt = 0; nt < 4; nt++) {
            const int row = m0 + warp_m + mt * 16 + (lane >> 2);
            const int col = n0 + warp_n + nt * 8 + (lane & 3) * 2;
            float* c0 = C + (size_t)row * ldc + col;
            float* c1 = C + (size_t)(row + 8) * ldc + col;
            *(float2*)c0 = make_float2(acc[mt][nt][0], acc[mt][nt][1]);
            *(float2*)c1 = make_float2(acc[mt][nt][2], acc[mt][nt][3]);
        }
    }
}

// ============================================================================
// converts: cvt_x also resets the per-replay accumulators (block 0)
// ============================================================================
__global__ __launch_bounds__(256) void cvt_x(const float* __restrict__ src,
                                             __half* __restrict__ dst)
{
    if (blockIdx.x == 0 && threadIdx.x == 0) {
        g_flag_count = 0;
        g_fix_delta = 0;
    }
    const size_t i = ((size_t)blockIdx.x * 256 + threadIdx.x) * 4;
    const float4 v = *(const float4*)(src + i);
    *(__half2*)(dst + i)     = __floats2half2_rn(v.x, v.y);
    *(__half2*)(dst + i + 2) = __floats2half2_rn(v.z, v.w);
}

__global__ __launch_bounds__(256) void cvt_w(
    const float* __restrict__ w1, __half* __restrict__ w1d,
    const float* __restrict__ w2, __half* __restrict__ w2d)
{
    const int half_grid = (int)gridDim.x >> 1;
    const bool second = blockIdx.x >= half_grid;
    const float* src = second ? w2 : w1;
    __half* dst = second ? w2d : w1d;
    const size_t i =
        ((size_t)(blockIdx.x - (second ? half_grid : 0)) * 256 + threadIdx.x) * 4;
    const float4 v = *(const float4*)(src + i);
    *(__half2*)(dst + i)     = __floats2half2_rn(v.x, v.y);
    *(__half2*)(dst + i + 2) = __floats2half2_rn(v.z, v.w);
}

// ============================================================================
// Two-phase fixup. Phase B stages operands through smem (coalesced by the
// warp) so lane 0's exact sequential ascending-k fp32 chain reads LDS.
// ============================================================================
__global__ __launch_bounds__(256) void fixup_kernel(
    const float* __restrict__ x, const float* __restrict__ w1)
{
    __shared__ float s_w[8][512];
    __shared__ float s_x[8][512];

    const unsigned int n = min(g_flag_count, (unsigned int)FLAG_CAP);
    const int lane = threadIdx.x & 31;
    const int wib  = threadIdx.x >> 5;
    const unsigned int warp = (blockIdx.x * 256 + threadIdx.x) >> 5;
    const unsigned int nwarps = (gridDim.x * 256) >> 5;
    int delta = 0;

    const float beta = (float)(1.0 - 1.0 / 20.0);
    const __half one  = __float2half(1.0f);
    const __half zero = __float2half(0.0f);

    for (unsigned int i = warp; i < n; i += nwarps) {
        const unsigned int idx = g_flags[i];
        const int    hid = (int)(idx & 2047u);
        const size_t bs  = idx >> 11;
        const size_t b   = bs >> 8;
        const size_t s   = bs & 255;
        const size_t bse = ((b * 4) * 256 + s) * 2048 + hid;
        const size_t ts  = 256UL * 2048UL;

        const float4* wrow = (const float4*)(w1 + (size_t)hid * 512);
        float w[16];
        #pragma unroll
        for (int j = 0; j < 4; j++) {
            const float4 wv = wrow[lane + j * 32];
            w[j * 4 + 0] = wv.x; w[j * 4 + 1] = wv.y;
            w[j * 4 + 2] = wv.z; w[j * 4 + 3] = wv.w;
        }

        // phase A: butterfly dots (all lanes end with identical sums)
        float accs[4];
        #pragma unroll
        for (int t = 0; t < 4; t++) {
            const float4* xrow =
                (const float4*)(x + (((b * 4 + t) * 256 + s) << 9));
            float a = 0.0f;
            #pragma unroll
            for (int j = 0; j < 4; j++) {
                const float4 xv = xrow[lane + j * 32];
                a = fmaf(xv.x, w[j * 4 + 0], a);
                a = fmaf(xv.y, w[j * 4 + 1], a);
                a = fmaf(xv.z, w[j * 4 + 2], a);
                a = fmaf(xv.w, w[j * 4 + 3], a);
            }
            #pragma unroll
            for (int o = 16; o; o >>= 1)
                a += __shfl_xor_sync(0xFFFFFFFFu, a, o);
            accs[t] = a;
        }

        // ambiguity test: identical on all lanes (accs are warp-uniform)
        bool amb = false;
        {
            float v = 0.0f;
            #pragma unroll
            for (int t = 0; t < 4; t++) {
                v = fmaf(beta, v, accs[t]);
                amb |= (fabsf(v - 1.0f) < AMB_EPS);
                v = (v > 1.0f) ? 0.0f : v;
            }
        }

        if (amb) {
            // phase B: stage rows into smem (coalesced), lane 0 exact serial
            #pragma unroll
            for (int j = 0; j < 4; j++) {
                const float4 wv = wrow[lane + j * 32];
                *(float4*)&s_w[wib][(lane + j * 32) * 4] = wv;
            }
            #pragma unroll
            for (int t = 0; t < 4; t++) {
                const float4* xrow =
                    (const float4*)(x + (((b * 4 + t) * 256 + s) << 9));
                #pragma unroll
                for (int j = 0; j < 4; j++) {
                    const float4 xv = xrow[lane + j * 32];
                    *(float4*)&s_x[wib][(lane + j * 32) * 4] = xv;
                }
                __syncwarp();
                if (lane == 0) {
                    float a = 0.0f;
                    #pragma unroll 8
                    for (int k = 0; k < 512; k++)
                        a = fmaf(s_x[wib][k], s_w[wib][k], a);
                    accs[t] = a;
                }
                __syncwarp();
            }
        }

        if (lane == 0) {
            float v = 0.0f;
            #pragma unroll
            for (int t = 0; t < 4; t++) {
                v = fmaf(beta, v, accs[t]);
                const bool fire = (v > 1.0f);
                const __half old = g_spk[bse + (size_t)t * ts];
                const bool oldf = (__half2float(old) > 0.5f);
                if (fire != oldf) {
                    g_spk[bse + (size_t)t * ts] = fire ? one : zero;
                    delta += fire ? 1 : -1;
                }
                v = fire ? 0.0f : v;
            }
        }
    }

    #pragma unroll
    for (int o = 16; o; o >>= 1) delta += __shfl_down_sync(0xFFFFFFFFu, delta, o);
    __shared__ int wsum[8];
    if (lane == 0) wsum[wib] = delta;
    __syncthreads();
    if (threadIdx.x == 0) {
        int tot = 0;
        #pragma unroll
        for (int w = 0; w < 8; w++) tot += wsum[w];
        if (tot != 0) atomicAdd(&g_fix_delta, tot);
    }
}

__global__ __launch_bounds__(1024) void rate_kernel(float* __restrict__ out_rate)
{
    long long s = 0;
    for (int i = threadIdx.x; i < 2048; i += 1024) s += g_partial[i];
    #pragma unroll
    for (int o = 16; o; o >>= 1) s += __shfl_down_sync(0xFFFFFFFFu, s, o);
    __shared__ long long sh[32];
    if ((threadIdx.x & 31) == 0) sh[threadIdx.x >> 5] = s;
    __syncthreads();
    if (threadIdx.x == 0) {
        long long tot = 0;
        #pragma unroll
        for (int w = 0; w < 32; w++) tot += sh[w];
        tot += g_fix_delta;
        *out_rate = (float)((double)tot / 33554432.0);
    }
}

// ============================================================================
extern "C" void kernel_launch(void* const* d_in, const int* in_sizes, int n_in,
                              void* d_out, int out_size)
{
    const float* x  = (const float*)d_in[0];
    const float* w1 = (const float*)d_in[1];
    const float* w2 = (const float*)d_in[2];
    float* out = (float*)d_out;

    __half *xh, *w1h, *w2h, *spk;
    cudaGetSymbolAddress((void**)&xh,  g_xh);
    cudaGetSymbolAddress((void**)&w1h, g_w1h);
    cudaGetSymbolAddress((void**)&w2h, g_w2h);
    cudaGetSymbolAddress((void**)&spk, g_spk);

    cudaFuncSetAttribute(gemm1_lif, cudaFuncAttributeMaxDynamicSharedMemorySize,
                         SMEM_ALLOC);
    cudaFuncSetAttribute(gemm_f16, cudaFuncAttributeMaxDynamicSharedMemorySize,
                         SMEM_ALLOC);

    // converts (cvt_x also resets flag/delta accumulators)
    cvt_x<<<8192, 256>>>(x, xh);
    cvt_w<<<2048, 256>>>(w1, w1h, w2, w2h);

    // GEMM1 + LIF fused
    gemm1_lif<<<dim3(16, 128), 256, SMEM_ALLOC>>>(xh, w1h);

    // two-phase fixup (smem-staged phase B), then rate
    fixup_kernel<<<1184, 256>>>(x, w1);
    rate_kernel<<<1, 1024>>>(out + (out_size - 1));

    // GEMM2
    gemm_f16<<<dim3(512 / BN, 16384 / BM), 256, SMEM_ALLOC>>>(
        spk, w2h, out, 512, 2048 / BK, 2048, 2048);
}